// round 1
// baseline (speedup 1.0000x reference)
#include <cuda_runtime.h>
#include <math.h>

#define HW 96
#define BATCH 2
#define C 720
#define M_TOT (BATCH*HW*HW)   // 18432
#define K3 (C*9)              // 6480
#define NPROTO 20

// ---------------- scratch (device globals; no allocs allowed) ----------------
__device__ float g_feats[M_TOT*C];   // NHWC concat+upsample result
__device__ float g_c[M_TOT*C];       // after cls head
__device__ float g_p1[M_TOT*C];      // after proj conv1 + bn + relu
__device__ float g_p2[M_TOT*C];      // after proj conv2
__device__ float g_wt1[K3*C];        // conv3x3 weights as [k=(q*720+cin)][cout]
__device__ float g_w1t[C*C];         // [cin][cout]
__device__ float g_w2t[C*C];
__device__ float g_proton[NPROTO*C]; // l2-normalized prototypes
__device__ float g_s1[C], g_t1[C], g_s2[C], g_t2[C]; // fused conv-bias+BN affine

// ---------------- concat + bilinear (align_corners=True) ----------------
__device__ __forceinline__ float bilerp(const float* __restrict__ src, int b, int Cin,
                                        int c, int S, int y, int x) {
    float sc = (float)(S - 1) / (float)(HW - 1);
    float fy = y * sc, fx = x * sc;
    int y0 = (int)floorf(fy); int x0 = (int)floorf(fx);
    int y1 = min(y0 + 1, S - 1); int x1 = min(x0 + 1, S - 1);
    float wy = fy - (float)y0, wx = fx - (float)x0;
    const float* p = src + ((b * Cin + c) * S) * S;
    float v00 = p[y0 * S + x0], v01 = p[y0 * S + x1];
    float v10 = p[y1 * S + x0], v11 = p[y1 * S + x1];
    return (v00 * (1.f - wx) + v01 * wx) * (1.f - wy)
         + (v10 * (1.f - wx) + v11 * wx) * wy;
}

__global__ void concat_kernel(const float* __restrict__ f1, const float* __restrict__ f2,
                              const float* __restrict__ f3, const float* __restrict__ f4) {
    int idx = blockIdx.x * blockDim.x + threadIdx.x;
    if (idx >= M_TOT * C) return;
    int c = idx % C;
    int m = idx / C;
    int x = m % HW; int y = (m / HW) % HW; int b = m / (HW * HW);
    float v;
    if (c < 48)        v = f1[((b * 48 + c) * HW + y) * HW + x];
    else if (c < 144)  v = bilerp(f2, b,  96, c - 48,  48, y, x);
    else if (c < 336)  v = bilerp(f3, b, 192, c - 144, 24, y, x);
    else               v = bilerp(f4, b, 384, c - 336, 12, y, x);
    g_feats[idx] = v;
}

// ---------------- weight / coefficient prep ----------------
__global__ void prep_w3(const float* __restrict__ w) {
    // cls_w [cout][cin][ky][kx] -> g_wt1[((ky*3+kx)*720+cin)*720 + cout]
    int idx = blockIdx.x * blockDim.x + threadIdx.x;
    if (idx >= K3 * C) return;
    int cout = idx % C;
    int k = idx / C;
    int cin = k % C;
    int q = k / C;
    g_wt1[idx] = w[(cout * C + cin) * 9 + q];
}

__global__ void prep_w1x1(const float* __restrict__ w1, const float* __restrict__ w2) {
    int idx = blockIdx.x * blockDim.x + threadIdx.x;
    if (idx >= C * C) return;
    int cout = idx % C;
    int cin = idx / C;
    g_w1t[idx] = w1[cout * C + cin];
    g_w2t[idx] = w2[cout * C + cin];
}

__global__ void prep_bn(const float* __restrict__ cls_b,
                        const float* __restrict__ g1, const float* __restrict__ b1,
                        const float* __restrict__ rm1, const float* __restrict__ rv1,
                        const float* __restrict__ pb1,
                        const float* __restrict__ g2, const float* __restrict__ b2,
                        const float* __restrict__ rm2, const float* __restrict__ rv2) {
    int n = blockIdx.x * blockDim.x + threadIdx.x;
    if (n >= C) return;
    float s1 = g1[n] * rsqrtf(rv1[n] + 1e-5f);
    g_s1[n] = s1;
    g_t1[n] = (cls_b[n] - rm1[n]) * s1 + b1[n];
    float s2 = g2[n] * rsqrtf(rv2[n] + 1e-5f);
    g_s2[n] = s2;
    g_t2[n] = (pb1[n] - rm2[n]) * s2 + b2[n];
}

__global__ void prep_proto(const float* __restrict__ pr) {
    int w = (blockIdx.x * blockDim.x + threadIdx.x) / 32;
    int lane = threadIdx.x & 31;
    if (w >= NPROTO) return;
    float ss = 0.f;
    for (int i = lane; i < C; i += 32) { float v = pr[w * C + i]; ss += v * v; }
    #pragma unroll
    for (int o = 16; o; o >>= 1) ss += __shfl_xor_sync(0xffffffffu, ss, o);
    float inv = 1.f / fmaxf(sqrtf(ss), 1e-12f);
    for (int i = lane; i < C; i += 32) g_proton[w * C + i] = pr[w * C + i] * inv;
}

// ---------------- fp32 tiled GEMM (128x128x16, 8x8/thread) ----------------
// MODE 0: implicit-im2col conv3x3 from g_feats, B=g_wt1, epi BN1+ReLU -> g_c
// MODE 1: A=g_c, B=g_w1t, epi BN2+ReLU -> g_p1
// MODE 2: A=g_p1, B=g_w2t, epi +proj_b2 -> g_p2
template <int MODE>
__global__ __launch_bounds__(256, 1) void gemm_k(const float* __restrict__ pb2) {
    constexpr int BM = 128, BN = 128, BK = 16;
    __shared__ __align__(16) float As[BK][BM + 4];
    __shared__ __align__(16) float Bs[BK][BN];
    const int tid = threadIdx.x;
    const int tx = tid & 15, ty = tid >> 4;
    const int m0 = blockIdx.y * BM;
    const int n0 = blockIdx.x * BN;

    const float* Aglob = (MODE == 0) ? g_feats : ((MODE == 1) ? g_c : g_p1);
    const float* Bglob = (MODE == 0) ? g_wt1 : ((MODE == 1) ? g_w1t : g_w2t);
    float* Cglob       = (MODE == 0) ? g_c : ((MODE == 1) ? g_p1 : g_p2);
    const int K = (MODE == 0) ? K3 : C;

    float acc[8][8];
    #pragma unroll
    for (int i = 0; i < 8; i++)
        #pragma unroll
        for (int j = 0; j < 8; j++) acc[i][j] = 0.f;

    for (int k0 = 0; k0 < K; k0 += BK) {
        // ---- load A tile (128 rows x 16 k) as 512 float4s ----
        #pragma unroll
        for (int l = 0; l < 2; l++) {
            int f = tid + l * 256;
            int row = f >> 2, col4 = f & 3;
            int m = m0 + row;
            int kk = k0 + col4 * 4;
            float4 v = make_float4(0.f, 0.f, 0.f, 0.f);
            if (MODE == 0) {
                // k order: (ky,kx,cin), cin fastest; 720 % 16 == 0 so a 16-slice
                // never crosses a (ky,kx) boundary.
                int q = kk / C; int cin = kk - q * C;
                int ky = q / 3, kx = q - ky * 3;
                int x = m % HW; int y = (m / HW) % HW; int b = m / (HW * HW);
                int yy = y + ky - 1, xx = x + kx - 1;
                if (yy >= 0 && yy < HW && xx >= 0 && xx < HW)
                    v = *(const float4*)(g_feats + ((b * HW + yy) * HW + xx) * C + cin);
            } else {
                v = *(const float4*)(Aglob + m * C + kk);
            }
            As[col4 * 4 + 0][row] = v.x;
            As[col4 * 4 + 1][row] = v.y;
            As[col4 * 4 + 2][row] = v.z;
            As[col4 * 4 + 3][row] = v.w;
        }
        // ---- load B tile (16 k x 128 n) ----
        #pragma unroll
        for (int l = 0; l < 2; l++) {
            int f = tid + l * 256;
            int row = f >> 5, col4 = f & 31;
            int kk = k0 + row;
            int n = n0 + col4 * 4;
            float4 v = make_float4(0.f, 0.f, 0.f, 0.f);
            if (n < C) v = *(const float4*)(Bglob + kk * C + n);
            *(float4*)&Bs[row][col4 * 4] = v;
        }
        __syncthreads();
        // ---- compute ----
        #pragma unroll
        for (int kk = 0; kk < BK; kk++) {
            float a[8], b[8];
            float4 t0 = *(const float4*)&As[kk][ty * 4];
            float4 t1 = *(const float4*)&As[kk][64 + ty * 4];
            a[0]=t0.x; a[1]=t0.y; a[2]=t0.z; a[3]=t0.w;
            a[4]=t1.x; a[5]=t1.y; a[6]=t1.z; a[7]=t1.w;
            float4 u0 = *(const float4*)&Bs[kk][tx * 4];
            float4 u1 = *(const float4*)&Bs[kk][64 + tx * 4];
            b[0]=u0.x; b[1]=u0.y; b[2]=u0.z; b[3]=u0.w;
            b[4]=u1.x; b[5]=u1.y; b[6]=u1.z; b[7]=u1.w;
            #pragma unroll
            for (int i = 0; i < 8; i++)
                #pragma unroll
                for (int j = 0; j < 8; j++)
                    acc[i][j] = fmaf(a[i], b[j], acc[i][j]);
        }
        __syncthreads();
    }
    // ---- epilogue ----
    #pragma unroll
    for (int i = 0; i < 8; i++) {
        int m = m0 + ty * 4 + (i & 3) + (i >> 2) * 64;
        #pragma unroll
        for (int j = 0; j < 8; j++) {
            int n = n0 + tx * 4 + (j & 3) + (j >> 2) * 64;
            if (n < C) {
                float v = acc[i][j];
                if (MODE == 0)      v = fmaxf(fmaf(v, g_s1[n], g_t1[n]), 0.f);
                else if (MODE == 1) v = fmaxf(fmaf(v, g_s2[n], g_t2[n]), 0.f);
                else                v = v + pb2[n];
                Cglob[m * C + n] = v;
            }
        }
    }
}

// ---------------- head: LN(720) + l2norm + proto dots + max + LN(2) ----------------
__global__ void head_kernel(const float* __restrict__ lng, const float* __restrict__ lnb,
                            const float* __restrict__ lmg, const float* __restrict__ lmb,
                            float* __restrict__ out) {
    int warp = (blockIdx.x * blockDim.x + threadIdx.x) >> 5;
    int lane = threadIdx.x & 31;
    if (warp >= M_TOT) return;
    const float* row = g_p2 + warp * C;

    float v[23];
    float s = 0.f, ss = 0.f;
    #pragma unroll
    for (int i = 0; i < 23; i++) {
        int idx = lane + i * 32;
        float x = (idx < C) ? row[idx] : 0.f;
        v[i] = x; s += x; ss += x * x;
    }
    #pragma unroll
    for (int o = 16; o; o >>= 1) {
        s  += __shfl_xor_sync(0xffffffffu, s, o);
        ss += __shfl_xor_sync(0xffffffffu, ss, o);
    }
    float mu = s / (float)C;
    float var = ss / (float)C - mu * mu;
    float rstd = rsqrtf(var + 1e-5f);

    float q = 0.f;
    #pragma unroll
    for (int i = 0; i < 23; i++) {
        int idx = lane + i * 32;
        float x = (idx < C) ? (v[i] - mu) * rstd * lng[idx] + lnb[idx] : 0.f;
        v[i] = x; q += x * x;
    }
    #pragma unroll
    for (int o = 16; o; o >>= 1) q += __shfl_xor_sync(0xffffffffu, q, o);
    float inv = 1.f / fmaxf(sqrtf(q), 1e-12f);

    float mx0 = -1e30f, mx1 = -1e30f;
    for (int p = 0; p < NPROTO; p++) {
        float d = 0.f;
        const float* pp = g_proton + p * C;
        #pragma unroll
        for (int i = 0; i < 23; i++) {
            int idx = lane + i * 32;
            if (idx < C) d += v[i] * pp[idx];
        }
        #pragma unroll
        for (int o = 16; o; o >>= 1) d += __shfl_xor_sync(0xffffffffu, d, o);
        d *= inv;
        if (p < 10) mx0 = fmaxf(mx0, d); else mx1 = fmaxf(mx1, d);
    }
    if (lane == 0) {
        float mu2 = 0.5f * (mx0 + mx1);
        float d0 = mx0 - mu2, d1 = mx1 - mu2;
        float var2 = 0.5f * (d0 * d0 + d1 * d1);
        float r2 = rsqrtf(var2 + 1e-5f);
        float o0 = d0 * r2 * lmg[0] + lmb[0];
        float o1 = d1 * r2 * lmg[1] + lmb[1];
        int m = warp;
        int x = m % HW, y = (m / HW) % HW, b = m / (HW * HW);
        out[((b * 2 + 0) * HW + y) * HW + x] = o0;
        out[((b * 2 + 1) * HW + y) * HW + x] = o1;
    }
}

// ---------------- launch ----------------
extern "C" void kernel_launch(void* const* d_in, const int* in_sizes, int n_in,
                              void* d_out, int out_size) {
    const float* feat1   = (const float*)d_in[0];
    const float* feat2   = (const float*)d_in[1];
    const float* feat3   = (const float*)d_in[2];
    const float* feat4   = (const float*)d_in[3];
    const float* cls_w   = (const float*)d_in[4];
    const float* cls_b   = (const float*)d_in[5];
    const float* cbn_g   = (const float*)d_in[6];
    const float* cbn_b   = (const float*)d_in[7];
    const float* cbn_rm  = (const float*)d_in[8];
    const float* cbn_rv  = (const float*)d_in[9];
    const float* pw1     = (const float*)d_in[10];
    const float* pb1     = (const float*)d_in[11];
    const float* pbn_g   = (const float*)d_in[12];
    const float* pbn_b   = (const float*)d_in[13];
    const float* pbn_rm  = (const float*)d_in[14];
    const float* pbn_rv  = (const float*)d_in[15];
    const float* pw2     = (const float*)d_in[16];
    const float* pb2     = (const float*)d_in[17];
    const float* lnf_g   = (const float*)d_in[18];
    const float* lnf_b   = (const float*)d_in[19];
    const float* lnm_g   = (const float*)d_in[20];
    const float* lnm_b   = (const float*)d_in[21];
    const float* protos  = (const float*)d_in[22];
    float* out = (float*)d_out;

    // prep (independent, small)
    concat_kernel<<<(M_TOT * C + 255) / 256, 256>>>(feat1, feat2, feat3, feat4);
    prep_w3<<<(K3 * C + 255) / 256, 256>>>(cls_w);
    prep_w1x1<<<(C * C + 255) / 256, 256>>>(pw1, pw2);
    prep_bn<<<3, 256>>>(cls_b, cbn_g, cbn_b, cbn_rm, cbn_rv,
                        pb1, pbn_g, pbn_b, pbn_rm, pbn_rv);
    prep_proto<<<NPROTO, 32>>>(protos);

    dim3 grid((C + 127) / 128, M_TOT / 128);  // (6, 144)
    gemm_k<0><<<grid, 256>>>(nullptr);
    gemm_k<1><<<grid, 256>>>(nullptr);
    gemm_k<2><<<grid, 256>>>(pb2);

    head_kernel<<<(M_TOT * 32 + 255) / 256, 256>>>(lnf_g, lnf_b, lnm_g, lnm_b, out);
    (void)in_sizes; (void)n_in; (void)out_size;
}

// round 2
// speedup vs baseline: 1.6063x; 1.6063x over previous
#include <cuda_runtime.h>
#include <math.h>

#define HW 96
#define BATCH 2
#define C 720
#define M_TOT (BATCH*HW*HW)   // 18432
#define K3 (C*9)              // 6480
#define NPROTO 20

// ---------------- scratch (device globals; no allocs allowed) ----------------
__device__ float g_feats[M_TOT*C];   // NHWC concat+upsample result
__device__ float g_c[M_TOT*C];       // after cls head
__device__ float g_p1[M_TOT*C];      // after proj conv1 + bn + relu
__device__ float g_p2[M_TOT*C];      // after proj conv2
__device__ float g_wt1[K3*C];        // conv3x3 weights as [k=(q*720+cin)][cout]
__device__ float g_w1t[C*C];         // [cin][cout]
__device__ float g_w2t[C*C];
__device__ float g_proton[NPROTO*C]; // l2-normalized prototypes
__device__ float g_s1[C], g_t1[C], g_s2[C], g_t2[C]; // fused conv-bias+BN affine

// ---------------- concat + bilinear (align_corners=True) ----------------
__device__ __forceinline__ float bilerp(const float* __restrict__ src, int b, int Cin,
                                        int c, int S, int y, int x) {
    float sc = (float)(S - 1) / (float)(HW - 1);
    float fy = y * sc, fx = x * sc;
    int y0 = (int)floorf(fy); int x0 = (int)floorf(fx);
    int y1 = min(y0 + 1, S - 1); int x1 = min(x0 + 1, S - 1);
    float wy = fy - (float)y0, wx = fx - (float)x0;
    const float* p = src + ((b * Cin + c) * S) * S;
    float v00 = p[y0 * S + x0], v01 = p[y0 * S + x1];
    float v10 = p[y1 * S + x0], v11 = p[y1 * S + x1];
    return (v00 * (1.f - wx) + v01 * wx) * (1.f - wy)
         + (v10 * (1.f - wx) + v11 * wx) * wy;
}

__global__ void concat_kernel(const float* __restrict__ f1, const float* __restrict__ f2,
                              const float* __restrict__ f3, const float* __restrict__ f4) {
    int idx = blockIdx.x * blockDim.x + threadIdx.x;
    if (idx >= M_TOT * C) return;
    int c = idx % C;
    int m = idx / C;
    int x = m % HW; int y = (m / HW) % HW; int b = m / (HW * HW);
    float v;
    if (c < 48)        v = f1[((b * 48 + c) * HW + y) * HW + x];
    else if (c < 144)  v = bilerp(f2, b,  96, c - 48,  48, y, x);
    else if (c < 336)  v = bilerp(f3, b, 192, c - 144, 24, y, x);
    else               v = bilerp(f4, b, 384, c - 336, 12, y, x);
    g_feats[idx] = v;
}

// ---------------- weight / coefficient prep ----------------
__global__ void prep_w3(const float* __restrict__ w) {
    // cls_w [cout][cin][ky][kx] -> g_wt1[((ky*3+kx)*720+cin)*720 + cout]
    int idx = blockIdx.x * blockDim.x + threadIdx.x;
    if (idx >= K3 * C) return;
    int cout = idx % C;
    int k = idx / C;
    int cin = k % C;
    int q = k / C;
    g_wt1[idx] = w[(cout * C + cin) * 9 + q];
}

__global__ void prep_w1x1(const float* __restrict__ w1, const float* __restrict__ w2) {
    int idx = blockIdx.x * blockDim.x + threadIdx.x;
    if (idx >= C * C) return;
    int cout = idx % C;
    int cin = idx / C;
    g_w1t[idx] = w1[cout * C + cin];
    g_w2t[idx] = w2[cout * C + cin];
}

__global__ void prep_bn(const float* __restrict__ cls_b,
                        const float* __restrict__ g1, const float* __restrict__ b1,
                        const float* __restrict__ rm1, const float* __restrict__ rv1,
                        const float* __restrict__ pb1,
                        const float* __restrict__ g2, const float* __restrict__ b2,
                        const float* __restrict__ rm2, const float* __restrict__ rv2) {
    int n = blockIdx.x * blockDim.x + threadIdx.x;
    if (n >= C) return;
    float s1 = g1[n] * rsqrtf(rv1[n] + 1e-5f);
    g_s1[n] = s1;
    g_t1[n] = (cls_b[n] - rm1[n]) * s1 + b1[n];
    float s2 = g2[n] * rsqrtf(rv2[n] + 1e-5f);
    g_s2[n] = s2;
    g_t2[n] = (pb1[n] - rm2[n]) * s2 + b2[n];
}

__global__ void prep_proto(const float* __restrict__ pr) {
    int w = (blockIdx.x * blockDim.x + threadIdx.x) / 32;
    int lane = threadIdx.x & 31;
    if (w >= NPROTO) return;
    float ss = 0.f;
    for (int i = lane; i < C; i += 32) { float v = pr[w * C + i]; ss += v * v; }
    #pragma unroll
    for (int o = 16; o; o >>= 1) ss += __shfl_xor_sync(0xffffffffu, ss, o);
    float inv = 1.f / fmaxf(sqrtf(ss), 1e-12f);
    for (int i = lane; i < C; i += 32) g_proton[w * C + i] = pr[w * C + i] * inv;
}

// ---------------- fp32 tiled GEMM (128x128x16, 8x8/thread) ----------------
// MODE 0: implicit-im2col conv3x3 from g_feats, B=g_wt1, epi BN1+ReLU -> g_c
// MODE 1: A=g_c, B=g_w1t, epi BN2+ReLU -> g_p1
// MODE 2: A=g_p1, B=g_w2t, epi +proj_b2 -> g_p2
template <int MODE>
__global__ __launch_bounds__(256, 1) void gemm_k(const float* __restrict__ pb2) {
    constexpr int BM = 128, BN = 128, BK = 16;
    __shared__ __align__(16) float As[BK][BM + 4];
    __shared__ __align__(16) float Bs[BK][BN];
    const int tid = threadIdx.x;
    const int tx = tid & 15, ty = tid >> 4;
    const int m0 = blockIdx.y * BM;
    const int n0 = blockIdx.x * BN;

    const float* Aglob = (MODE == 0) ? g_feats : ((MODE == 1) ? g_c : g_p1);
    const float* Bglob = (MODE == 0) ? g_wt1 : ((MODE == 1) ? g_w1t : g_w2t);
    float* Cglob       = (MODE == 0) ? g_c : ((MODE == 1) ? g_p1 : g_p2);
    const int K = (MODE == 0) ? K3 : C;

    float acc[8][8];
    #pragma unroll
    for (int i = 0; i < 8; i++)
        #pragma unroll
        for (int j = 0; j < 8; j++) acc[i][j] = 0.f;

    for (int k0 = 0; k0 < K; k0 += BK) {
        // ---- load A tile (128 rows x 16 k) as 512 float4s ----
        #pragma unroll
        for (int l = 0; l < 2; l++) {
            int f = tid + l * 256;
            int row = f >> 2, col4 = f & 3;
            int m = m0 + row;
            int kk = k0 + col4 * 4;
            float4 v = make_float4(0.f, 0.f, 0.f, 0.f);
            if (MODE == 0) {
                // k order: (ky,kx,cin), cin fastest; 720 % 16 == 0 so a 16-slice
                // never crosses a (ky,kx) boundary.
                int q = kk / C; int cin = kk - q * C;
                int ky = q / 3, kx = q - ky * 3;
                int x = m % HW; int y = (m / HW) % HW; int b = m / (HW * HW);
                int yy = y + ky - 1, xx = x + kx - 1;
                if (yy >= 0 && yy < HW && xx >= 0 && xx < HW)
                    v = *(const float4*)(g_feats + ((b * HW + yy) * HW + xx) * C + cin);
            } else {
                v = *(const float4*)(Aglob + m * C + kk);
            }
            As[col4 * 4 + 0][row] = v.x;
            As[col4 * 4 + 1][row] = v.y;
            As[col4 * 4 + 2][row] = v.z;
            As[col4 * 4 + 3][row] = v.w;
        }
        // ---- load B tile (16 k x 128 n) ----
        #pragma unroll
        for (int l = 0; l < 2; l++) {
            int f = tid + l * 256;
            int row = f >> 5, col4 = f & 31;
            int kk = k0 + row;
            int n = n0 + col4 * 4;
            float4 v = make_float4(0.f, 0.f, 0.f, 0.f);
            if (n < C) v = *(const float4*)(Bglob + kk * C + n);
            *(float4*)&Bs[row][col4 * 4] = v;
        }
        __syncthreads();
        // ---- compute ----
        #pragma unroll
        for (int kk = 0; kk < BK; kk++) {
            float a[8], b[8];
            float4 t0 = *(const float4*)&As[kk][ty * 4];
            float4 t1 = *(const float4*)&As[kk][64 + ty * 4];
            a[0]=t0.x; a[1]=t0.y; a[2]=t0.z; a[3]=t0.w;
            a[4]=t1.x; a[5]=t1.y; a[6]=t1.z; a[7]=t1.w;
            float4 u0 = *(const float4*)&Bs[kk][tx * 4];
            float4 u1 = *(const float4*)&Bs[kk][64 + tx * 4];
            b[0]=u0.x; b[1]=u0.y; b[2]=u0.z; b[3]=u0.w;
            b[4]=u1.x; b[5]=u1.y; b[6]=u1.z; b[7]=u1.w;
            #pragma unroll
            for (int i = 0; i < 8; i++)
                #pragma unroll
                for (int j = 0; j < 8; j++)
                    acc[i][j] = fmaf(a[i], b[j], acc[i][j]);
        }
        __syncthreads();
    }
    // ---- epilogue ----
    #pragma unroll
    for (int i = 0; i < 8; i++) {
        int m = m0 + ty * 4 + (i & 3) + (i >> 2) * 64;
        #pragma unroll
        for (int j = 0; j < 8; j++) {
            int n = n0 + tx * 4 + (j & 3) + (j >> 2) * 64;
            if (n < C) {
                float v = acc[i][j];
                if (MODE == 0)      v = fmaxf(fmaf(v, g_s1[n], g_t1[n]), 0.f);
                else if (MODE == 1) v = fmaxf(fmaf(v, g_s2[n], g_t2[n]), 0.f);
                else                v = v + pb2[n];
                Cglob[m * C + n] = v;
            }
        }
    }
}

// ---------------- head: LN(720) + l2norm + proto dots + max + LN(2) ----------------
__global__ void head_kernel(const float* __restrict__ lng, const float* __restrict__ lnb,
                            const float* __restrict__ lmg, const float* __restrict__ lmb,
                            float* __restrict__ out) {
    int warp = (blockIdx.x * blockDim.x + threadIdx.x) >> 5;
    int lane = threadIdx.x & 31;
    if (warp >= M_TOT) return;
    const float* row = g_p2 + warp * C;

    float v[23];
    float s = 0.f, ss = 0.f;
    #pragma unroll
    for (int i = 0; i < 23; i++) {
        int idx = lane + i * 32;
        float x = (idx < C) ? row[idx] : 0.f;
        v[i] = x; s += x; ss += x * x;
    }
    #pragma unroll
    for (int o = 16; o; o >>= 1) {
        s  += __shfl_xor_sync(0xffffffffu, s, o);
        ss += __shfl_xor_sync(0xffffffffu, ss, o);
    }
    float mu = s / (float)C;
    float var = ss / (float)C - mu * mu;
    float rstd = rsqrtf(var + 1e-5f);

    float q = 0.f;
    #pragma unroll
    for (int i = 0; i < 23; i++) {
        int idx = lane + i * 32;
        float x = (idx < C) ? (v[i] - mu) * rstd * lng[idx] + lnb[idx] : 0.f;
        v[i] = x; q += x * x;
    }
    #pragma unroll
    for (int o = 16; o; o >>= 1) q += __shfl_xor_sync(0xffffffffu, q, o);
    float inv = 1.f / fmaxf(sqrtf(q), 1e-12f);

    float mx0 = -1e30f, mx1 = -1e30f;
    for (int p = 0; p < NPROTO; p++) {
        float d = 0.f;
        const float* pp = g_proton + p * C;
        #pragma unroll
        for (int i = 0; i < 23; i++) {
            int idx = lane + i * 32;
            if (idx < C) d += v[i] * pp[idx];
        }
        #pragma unroll
        for (int o = 16; o; o >>= 1) d += __shfl_xor_sync(0xffffffffu, d, o);
        d *= inv;
        if (p < 10) mx0 = fmaxf(mx0, d); else mx1 = fmaxf(mx1, d);
    }
    if (lane == 0) {
        float mu2 = 0.5f * (mx0 + mx1);
        float d0 = mx0 - mu2, d1 = mx1 - mu2;
        float var2 = 0.5f * (d0 * d0 + d1 * d1);
        float r2 = rsqrtf(var2 + 1e-5f);
        float o0 = d0 * r2 * lmg[0] + lmb[0];
        float o1 = d1 * r2 * lmg[1] + lmb[1];
        int m = warp;
        int x = m % HW, y = (m / HW) % HW, b = m / (HW * HW);
        out[((b * 2 + 0) * HW + y) * HW + x] = o0;
        out[((b * 2 + 1) * HW + y) * HW + x] = o1;
    }
}

// ---------------- launch ----------------
extern "C" void kernel_launch(void* const* d_in, const int* in_sizes, int n_in,
                              void* d_out, int out_size) {
    const float* feat1   = (const float*)d_in[0];
    const float* feat2   = (const float*)d_in[1];
    const float* feat3   = (const float*)d_in[2];
    const float* feat4   = (const float*)d_in[3];
    const float* cls_w   = (const float*)d_in[4];
    const float* cls_b   = (const float*)d_in[5];
    const float* cbn_g   = (const float*)d_in[6];
    const float* cbn_b   = (const float*)d_in[7];
    const float* cbn_rm  = (const float*)d_in[8];
    const float* cbn_rv  = (const float*)d_in[9];
    const float* pw1     = (const float*)d_in[10];
    const float* pb1     = (const float*)d_in[11];
    const float* pbn_g   = (const float*)d_in[12];
    const float* pbn_b   = (const float*)d_in[13];
    const float* pbn_rm  = (const float*)d_in[14];
    const float* pbn_rv  = (const float*)d_in[15];
    const float* pw2     = (const float*)d_in[16];
    const float* pb2     = (const float*)d_in[17];
    const float* lnf_g   = (const float*)d_in[18];
    const float* lnf_b   = (const float*)d_in[19];
    const float* lnm_g   = (const float*)d_in[20];
    const float* lnm_b   = (const float*)d_in[21];
    const float* protos  = (const float*)d_in[22];
    float* out = (float*)d_out;

    // prep (independent, small)
    concat_kernel<<<(M_TOT * C + 255) / 256, 256>>>(feat1, feat2, feat3, feat4);
    prep_w3<<<(K3 * C + 255) / 256, 256>>>(cls_w);
    prep_w1x1<<<(C * C + 255) / 256, 256>>>(pw1, pw2);
    prep_bn<<<3, 256>>>(cls_b, cbn_g, cbn_b, cbn_rm, cbn_rv,
                        pb1, pbn_g, pbn_b, pbn_rm, pbn_rv);
    prep_proto<<<NPROTO, 32>>>(protos);

    dim3 grid((C + 127) / 128, M_TOT / 128);  // (6, 144)
    gemm_k<0><<<grid, 256>>>(nullptr);
    gemm_k<1><<<grid, 256>>>(nullptr);
    gemm_k<2><<<grid, 256>>>(pb2);

    head_kernel<<<(M_TOT * 32 + 255) / 256, 256>>>(lnf_g, lnf_b, lnm_g, lnm_b, out);
    (void)in_sizes; (void)n_in; (void)out_size;
}

// round 4
// speedup vs baseline: 3.2942x; 2.0509x over previous
#include <cuda_runtime.h>
#include <cuda_bf16.h>
#include <math.h>
#include <stdint.h>

#define HW 96
#define C0 720
#define CP 768
#define M_TOT 18432
#define KC (9*CP)
#define NPROTO 20
#define BM 128
#define BN 144
#define BK 32
#define ROWB 80                      // padded row stride in bytes (40 bf16)
#define A_PL (128*ROWB)              // 10240
#define B_PL (144*ROWB)              // 11520
#define STG (2*A_PL + 2*B_PL)        // 43520
#define NSTAGE 3
#define SMEM_DYN (NSTAGE*STG)        // 130560
#define NCHUNK 2176                  // 16B cp.async chunks per stage

__device__ __nv_bfloat16 g_fh[M_TOT*CP], g_fl[M_TOT*CP];
__device__ __nv_bfloat16 g_wch[C0*KC], g_wcl[C0*KC];
__device__ __nv_bfloat16 g_w1h[C0*CP], g_w1l[C0*CP];
__device__ __nv_bfloat16 g_w2h[C0*CP], g_w2l[C0*CP];
__device__ __nv_bfloat16 g_ch[M_TOT*CP], g_cl[M_TOT*CP];
__device__ __nv_bfloat16 g_p1h[M_TOT*CP], g_p1l[M_TOT*CP];
__device__ float g_p2[M_TOT*C0];
__device__ float g_s1[C0], g_t1[C0], g_s2[C0], g_t2[C0];
__device__ float g_proton[NPROTO*C0];

__device__ __forceinline__ uint32_t smem_u32(const void* p){
    uint32_t a;
    asm("{ .reg .u64 t; cvta.to.shared.u64 t, %1; cvt.u32.u64 %0, t; }" : "=r"(a) : "l"(p));
    return a;
}
__device__ __forceinline__ void ldsm4(uint32_t* r, uint32_t a){
    asm volatile("ldmatrix.sync.aligned.m8n8.x4.shared.b16 {%0,%1,%2,%3}, [%4];"
        : "=r"(r[0]), "=r"(r[1]), "=r"(r[2]), "=r"(r[3]) : "r"(a));
}
__device__ __forceinline__ void ldsm2(uint32_t* r, uint32_t a){
    asm volatile("ldmatrix.sync.aligned.m8n8.x2.shared.b16 {%0,%1}, [%2];"
        : "=r"(r[0]), "=r"(r[1]) : "r"(a));
}
__device__ __forceinline__ void mma16816(float* c, const uint32_t* a, const uint32_t* b){
    asm volatile("mma.sync.aligned.m16n8k16.row.col.f32.bf16.bf16.f32 "
        "{%0,%1,%2,%3}, {%4,%5,%6,%7}, {%8,%9}, {%0,%1,%2,%3};"
        : "+f"(c[0]), "+f"(c[1]), "+f"(c[2]), "+f"(c[3])
        : "r"(a[0]), "r"(a[1]), "r"(a[2]), "r"(a[3]), "r"(b[0]), "r"(b[1]));
}
__device__ __forceinline__ void cpa16(uint32_t dst, const void* src, int sz){
    asm volatile("cp.async.cg.shared.global [%0], [%1], 16, %2;" :: "r"(dst), "l"(src), "r"(sz));
}
__device__ __forceinline__ void split_bf(float v, __nv_bfloat16& h, __nv_bfloat16& l){
    h = __float2bfloat16(v); l = __float2bfloat16(v - __bfloat162float(h));
}

// ---------------- concat + bilinear (align_corners=True) ----------------
__device__ __forceinline__ float bilerp(const float* __restrict__ s, int b, int Ci, int c, int S, int y, int x){
    float sc = (float)(S-1)/(float)(HW-1);
    float fy = y*sc, fx = x*sc;
    int y0 = (int)floorf(fy), x0 = (int)floorf(fx);
    int y1 = min(y0+1, S-1), x1 = min(x0+1, S-1);
    float wy = fy-y0, wx = fx-x0;
    const float* p = s + ((b*Ci+c)*S)*S;
    float v00=p[y0*S+x0], v01=p[y0*S+x1], v10=p[y1*S+x0], v11=p[y1*S+x1];
    return (v00*(1.f-wx)+v01*wx)*(1.f-wy) + (v10*(1.f-wx)+v11*wx)*wy;
}
__global__ void concat_kernel(const float* __restrict__ f1, const float* __restrict__ f2,
                              const float* __restrict__ f3, const float* __restrict__ f4){
    int idx = blockIdx.x*blockDim.x + threadIdx.x;
    if (idx >= M_TOT*CP) return;
    int c = idx % CP, m = idx / CP;
    float v = 0.f;
    if (c < C0){
        int x = m%HW, y = (m/HW)%HW, b = m/(HW*HW);
        if (c < 48)       v = f1[((b*48+c)*HW+y)*HW+x];
        else if (c < 144) v = bilerp(f2,b, 96,c-48, 48,y,x);
        else if (c < 336) v = bilerp(f3,b,192,c-144,24,y,x);
        else              v = bilerp(f4,b,384,c-336,12,y,x);
    }
    __nv_bfloat16 h,l; split_bf(v,h,l);
    g_fh[idx]=h; g_fl[idx]=l;
}

// ---------------- prep ----------------
__global__ void prep_w3(const float* __restrict__ w){
    int idx = blockIdx.x*blockDim.x + threadIdx.x;
    if (idx >= C0*KC) return;
    int cout = idx / KC, k = idx % KC;
    int q = k / CP, cin = k % CP;
    float v = (cin < C0) ? w[(cout*C0+cin)*9+q] : 0.f;
    __nv_bfloat16 h,l; split_bf(v,h,l);
    g_wch[idx]=h; g_wcl[idx]=l;
}
__global__ void prep_w1x1(const float* __restrict__ w1, const float* __restrict__ w2){
    int idx = blockIdx.x*blockDim.x + threadIdx.x;
    if (idx >= C0*CP) return;
    int cout = idx / CP, cin = idx % CP;
    __nv_bfloat16 h,l;
    float a = (cin<C0)? w1[cout*C0+cin] : 0.f;
    split_bf(a,h,l); g_w1h[idx]=h; g_w1l[idx]=l;
    float b = (cin<C0)? w2[cout*C0+cin] : 0.f;
    split_bf(b,h,l); g_w2h[idx]=h; g_w2l[idx]=l;
}
__global__ void pad_zero(){
    int idx = blockIdx.x*blockDim.x + threadIdx.x;
    if (idx >= M_TOT*(CP-C0)) return;
    int m = idx/(CP-C0), c = C0 + idx%(CP-C0);
    __nv_bfloat16 z = __float2bfloat16(0.f);
    g_ch[m*CP+c]=z; g_cl[m*CP+c]=z; g_p1h[m*CP+c]=z; g_p1l[m*CP+c]=z;
}
__global__ void prep_bn(const float* __restrict__ cb, const float* __restrict__ g1, const float* __restrict__ b1,
                        const float* __restrict__ rm1, const float* __restrict__ rv1, const float* __restrict__ pb1,
                        const float* __restrict__ g2, const float* __restrict__ b2,
                        const float* __restrict__ rm2, const float* __restrict__ rv2){
    int n = blockIdx.x*blockDim.x + threadIdx.x;
    if (n >= C0) return;
    float s1 = g1[n]*rsqrtf(rv1[n]+1e-5f);
    g_s1[n]=s1; g_t1[n]=(cb[n]-rm1[n])*s1+b1[n];
    float s2 = g2[n]*rsqrtf(rv2[n]+1e-5f);
    g_s2[n]=s2; g_t2[n]=(pb1[n]-rm2[n])*s2+b2[n];
}
__global__ void prep_proto(const float* __restrict__ pr){
    int w = blockIdx.x, lane = threadIdx.x & 31;
    float ss = 0.f;
    for (int i=lane;i<C0;i+=32){ float v=pr[w*C0+i]; ss+=v*v; }
    #pragma unroll
    for (int o=16;o;o>>=1) ss += __shfl_xor_sync(0xffffffffu, ss, o);
    float inv = 1.f/fmaxf(sqrtf(ss),1e-12f);
    for (int i=lane;i<C0;i+=32) g_proton[w*C0+i] = pr[w*C0+i]*inv;
}

// ---------------- bf16 mma.sync GEMM, 3xBF16 split, 3-stage cp.async ----------------
// MODE 0: A=im2col(g_f*), B=g_wc*, epi BN1+ReLU -> g_c*
// MODE 1: A=g_c*,  B=g_w1*, epi BN2+ReLU -> g_p1*
// MODE 2: A=g_p1*, B=g_w2*, epi +pb2 -> g_p2 (fp32)
template<int MODE>
__global__ __launch_bounds__(256,1) void gemm_mma(const float* __restrict__ pb2){
    extern __shared__ __align__(128) char smem[];
    const uint32_t su = smem_u32(smem);
    const int tid = threadIdx.x, lane = tid&31, wid = tid>>5;
    const int wm = wid&3, wn = wid>>2;          // 4 x 2 warp grid
    const int m0 = blockIdx.y*BM, n0 = blockIdx.x*BN;
    const int Kdim = (MODE==0)? KC : CP;
    const int nIter = Kdim/BK;                  // 216 or 24

    const char* pAh = (const char*)((MODE==0)? g_fh : (MODE==1)? g_ch : g_p1h);
    const char* pAl = (const char*)((MODE==0)? g_fl : (MODE==1)? g_cl : g_p1l);
    const char* pBh = (const char*)((MODE==0)? g_wch : (MODE==1)? g_w1h : g_w2h);
    const char* pBl = (const char*)((MODE==0)? g_wcl : (MODE==1)? g_w1l : g_w2l);

    // ---- per-slot precompute (9 chunk slots per thread) ----
    bool valid[9], isA[9];
    int pl[9], dstOff[9], base[9], py[9], px[9];
    #pragma unroll
    for (int p=0;p<9;p++){
        int i = tid + p*256;
        valid[p] = (i < NCHUNK);
        isA[p]=false; pl[p]=0; dstOff[p]=0; base[p]=0; py[p]=0; px[p]=0;
        if (!valid[p]) continue;
        if (i < 1024){
            isA[p] = true;
            int plane = i>>9, rem = i&511, r = rem>>2, c = rem&3;
            pl[p] = plane;
            dstOff[p] = plane*A_PL + r*ROWB + c*16;
            int m = m0 + r;
            if (MODE==0){
                int b = m/(HW*HW), rm = m%(HW*HW);
                int y = rm/HW, x = rm%HW;
                py[p]=y; px[p]=x;
                base[p] = ((b*HW+y)*HW+x)*CP + c*8;
            } else {
                base[p] = m*CP + c*8;
            }
        } else {
            int j = i-1024;
            int plane = (j>=576)?1:0, rem = j%576, r = rem>>2, c = rem&3;
            pl[p] = plane;
            dstOff[p] = 2*A_PL + plane*B_PL + r*ROWB + c*16;
            base[p] = (n0+r)*Kdim + c*8;
        }
    }

    auto load_stage = [&](int it){
        int s = it % NSTAGE;
        uint32_t sb = su + s*STG;
        int kfull = it*BK;
        int addA, dy=0, dx=0;
        if (MODE==0){
            int tap = kfull/CP;
            int cin0 = kfull - tap*CP;
            dy = tap/3 - 1; dx = tap%3 - 1;
            addA = (dy*HW+dx)*CP + cin0;
        } else addA = kfull;
        #pragma unroll
        for (int p=0;p<9;p++){
            if (!valid[p]) continue;
            uint32_t dst = sb + dstOff[p];
            if (isA[p]){
                int sz = 16;
                const char* src = (pl[p]? pAl : pAh) + (long)(base[p] + addA)*2;
                if (MODE==0){
                    if (!(((unsigned)(py[p]+dy) < HW) && ((unsigned)(px[p]+dx) < HW))){
                        sz = 0; src = pAh;
                    }
                }
                cpa16(dst, src, sz);
            } else {
                const char* src = (pl[p]? pBl : pBh) + (long)(base[p] + kfull)*2;
                cpa16(dst, src, 16);
            }
        }
        asm volatile("cp.async.commit_group;" ::: "memory");
    };

    float acc[2][9][4];
    #pragma unroll
    for (int a=0;a<2;a++)
        #pragma unroll
        for (int b=0;b<9;b++)
            #pragma unroll
            for (int c=0;c<4;c++) acc[a][b][c]=0.f;

    load_stage(0);
    if (nIter > 1) load_stage(1);

    for (int it=0; it<nIter; ++it){
        if (it+2 < nIter) load_stage(it+2);
        int ahead = nIter-1-it; if (ahead>2) ahead=2;
        if (ahead==2)      asm volatile("cp.async.wait_group 2;" ::: "memory");
        else if (ahead==1) asm volatile("cp.async.wait_group 1;" ::: "memory");
        else               asm volatile("cp.async.wait_group 0;" ::: "memory");
        __syncthreads();

        uint32_t sb = su + (it % NSTAGE)*STG;
        #pragma unroll
        for (int k16=0;k16<2;k16++){
            uint32_t ah[2][4], al[2][4];
            #pragma unroll
            for (int mt=0;mt<2;mt++){
                uint32_t row = wm*32 + mt*16 + (lane&15);
                uint32_t col = k16*16 + (lane>>4)*8;
                uint32_t ad = sb + row*ROWB + col*2;
                ldsm4(ah[mt], ad);
                ldsm4(al[mt], ad + A_PL);
            }
            #pragma unroll
            for (int np=0;np<5;np++){
                if (np<4){
                    uint32_t n = wn*72 + np*16 + (lane>>4)*8 + (lane&7);
                    uint32_t kc = k16*16 + ((lane>>3)&1)*8;
                    uint32_t ad = sb + 2*A_PL + n*ROWB + kc*2;
                    uint32_t bh[4], bl[4];
                    ldsm4(bh, ad);
                    ldsm4(bl, ad + B_PL);
                    #pragma unroll
                    for (int h=0;h<2;h++){
                        int nt = np*2+h;
                        #pragma unroll
                        for (int mt=0;mt<2;mt++){
                            mma16816(acc[mt][nt], ah[mt], bh+2*h);
                            mma16816(acc[mt][nt], ah[mt], bl+2*h);
                            mma16816(acc[mt][nt], al[mt], bh+2*h);
                        }
                    }
                } else {
                    uint32_t n = wn*72 + 64 + (lane&7);
                    uint32_t kc = k16*16 + ((lane>>3)&1)*8;
                    uint32_t ad = sb + 2*A_PL + n*ROWB + kc*2;
                    uint32_t bh[2], bl[2];
                    ldsm2(bh, ad);
                    ldsm2(bl, ad + B_PL);
                    #pragma unroll
                    for (int mt=0;mt<2;mt++){
                        mma16816(acc[mt][8], ah[mt], bh);
                        mma16816(acc[mt][8], ah[mt], bl);
                        mma16816(acc[mt][8], al[mt], bh);
                    }
                }
            }
        }
        __syncthreads();
    }

    // ---- epilogue ----
    #pragma unroll
    for (int mt=0;mt<2;mt++){
        #pragma unroll
        for (int nt=0;nt<9;nt++){
            #pragma unroll
            for (int h=0;h<2;h++){
                int m = m0 + wm*32 + mt*16 + (lane>>2) + h*8;
                int n = n0 + wn*72 + nt*8 + (lane&3)*2;
                float v0 = acc[mt][nt][2*h], v1 = acc[mt][nt][2*h+1];
                if (MODE==2){
                    float2 o; o.x = v0 + pb2[n]; o.y = v1 + pb2[n+1];
                    *(float2*)(g_p2 + (long)m*C0 + n) = o;
                } else {
                    const float* S = (MODE==0)? g_s1 : g_s2;
                    const float* T = (MODE==0)? g_t1 : g_t2;
                    __nv_bfloat16* Oh = (MODE==0)? g_ch : g_p1h;
                    __nv_bfloat16* Ol = (MODE==0)? g_cl : g_p1l;
                    float r0 = fmaxf(fmaf(v0, S[n],   T[n]),   0.f);
                    float r1 = fmaxf(fmaf(v1, S[n+1], T[n+1]), 0.f);
                    __nv_bfloat16 h0,l0,h1,l1;
                    split_bf(r0,h0,l0); split_bf(r1,h1,l1);
                    uint32_t ph = (uint32_t)__bfloat16_as_ushort(h0) | ((uint32_t)__bfloat16_as_ushort(h1)<<16);
                    uint32_t plv = (uint32_t)__bfloat16_as_ushort(l0) | ((uint32_t)__bfloat16_as_ushort(l1)<<16);
                    *(uint32_t*)(Oh + (long)m*CP + n) = ph;
                    *(uint32_t*)(Ol + (long)m*CP + n) = plv;
                }
            }
        }
    }
}

// ---------------- head ----------------
__global__ void head_kernel(const float* __restrict__ lng, const float* __restrict__ lnb,
                            const float* __restrict__ lmg, const float* __restrict__ lmb,
                            float* __restrict__ out){
    int warp = (blockIdx.x*blockDim.x + threadIdx.x)>>5;
    int lane = threadIdx.x & 31;
    if (warp >= M_TOT) return;
    const float* row = g_p2 + (long)warp*C0;
    float v[23]; float s=0.f, ss=0.f;
    #pragma unroll
    for (int i=0;i<23;i++){
        int idx = lane + i*32;
        float x = (idx<C0)? row[idx] : 0.f;
        v[i]=x; s+=x; ss+=x*x;
    }
    #pragma unroll
    for (int o=16;o;o>>=1){ s+=__shfl_xor_sync(0xffffffffu,s,o); ss+=__shfl_xor_sync(0xffffffffu,ss,o); }
    float mu = s/(float)C0;
    float rstd = rsqrtf(ss/(float)C0 - mu*mu + 1e-5f);
    float q = 0.f;
    #pragma unroll
    for (int i=0;i<23;i++){
        int idx = lane + i*32;
        float x = (idx<C0)? (v[i]-mu)*rstd*lng[idx]+lnb[idx] : 0.f;
        v[i]=x; q+=x*x;
    }
    #pragma unroll
    for (int o=16;o;o>>=1) q+=__shfl_xor_sync(0xffffffffu,q,o);
    float inv = 1.f/fmaxf(sqrtf(q),1e-12f);
    float mx0=-1e30f, mx1=-1e30f;
    for (int p=0;p<NPROTO;p++){
        float d=0.f;
        const float* pp = g_proton + p*C0;
        #pragma unroll
        for (int i=0;i<23;i++){
            int idx = lane + i*32;
            if (idx<C0) d += v[i]*pp[idx];
        }
        #pragma unroll
        for (int o=16;o;o>>=1) d+=__shfl_xor_sync(0xffffffffu,d,o);
        d *= inv;
        if (p<10) mx0=fmaxf(mx0,d); else mx1=fmaxf(mx1,d);
    }
    if (lane==0){
        float mu2 = 0.5f*(mx0+mx1);
        float d0 = mx0-mu2, d1 = mx1-mu2;
        float r2 = rsqrtf(0.5f*(d0*d0+d1*d1)+1e-5f);
        int m = warp;
        int x = m%HW, y = (m/HW)%HW, b = m/(HW*HW);
        out[((b*2+0)*HW+y)*HW+x] = d0*r2*lmg[0]+lmb[0];
        out[((b*2+1)*HW+y)*HW+x] = d1*r2*lmg[1]+lmb[1];
    }
}

extern "C" void kernel_launch(void* const* d_in, const int* in_sizes, int n_in,
                              void* d_out, int out_size){
    const float* feat1=(const float*)d_in[0];  const float* feat2=(const float*)d_in[1];
    const float* feat3=(const float*)d_in[2];  const float* feat4=(const float*)d_in[3];
    const float* cls_w=(const float*)d_in[4];  const float* cls_b=(const float*)d_in[5];
    const float* cbn_g=(const float*)d_in[6];  const float* cbn_b=(const float*)d_in[7];
    const float* cbn_rm=(const float*)d_in[8]; const float* cbn_rv=(const float*)d_in[9];
    const float* pw1=(const float*)d_in[10];   const float* pb1=(const float*)d_in[11];
    const float* pbn_g=(const float*)d_in[12]; const float* pbn_b=(const float*)d_in[13];
    const float* pbn_rm=(const float*)d_in[14];const float* pbn_rv=(const float*)d_in[15];
    const float* pw2=(const float*)d_in[16];   const float* pb2=(const float*)d_in[17];
    const float* lnf_g=(const float*)d_in[18]; const float* lnf_b=(const float*)d_in[19];
    const float* lnm_g=(const float*)d_in[20]; const float* lnm_b=(const float*)d_in[21];
    const float* protos=(const float*)d_in[22];
    float* out = (float*)d_out;

    static int smem_set = 0;
    if (!smem_set){
        cudaFuncSetAttribute(gemm_mma<0>, cudaFuncAttributeMaxDynamicSharedMemorySize, SMEM_DYN);
        cudaFuncSetAttribute(gemm_mma<1>, cudaFuncAttributeMaxDynamicSharedMemorySize, SMEM_DYN);
        cudaFuncSetAttribute(gemm_mma<2>, cudaFuncAttributeMaxDynamicSharedMemorySize, SMEM_DYN);
        smem_set = 1;
    }

    concat_kernel<<<(M_TOT*CP+255)/256, 256>>>(feat1, feat2, feat3, feat4);
    prep_w3<<<(C0*KC+255)/256, 256>>>(cls_w);
    prep_w1x1<<<(C0*CP+255)/256, 256>>>(pw1, pw2);
    pad_zero<<<(M_TOT*(CP-C0)+255)/256, 256>>>();
    prep_bn<<<3, 256>>>(cls_b, cbn_g, cbn_b, cbn_rm, cbn_rv, pb1, pbn_g, pbn_b, pbn_rm, pbn_rv);
    prep_proto<<<NPROTO, 32>>>(protos);

    dim3 grid(BN==144 ? 5 : (C0+BN-1)/BN, M_TOT/BM);  // (5,144)
    gemm_mma<0><<<grid, 256, SMEM_DYN>>>(nullptr);
    gemm_mma<1><<<grid, 256, SMEM_DYN>>>(nullptr);
    gemm_mma<2><<<grid, 256, SMEM_DYN>>>(pb2);

    head_kernel<<<(M_TOT*32+255)/256, 256>>>(lnf_g, lnf_b, lnm_g, lnm_b, out);
    (void)in_sizes; (void)n_in; (void)out_size;
}

// round 5
// speedup vs baseline: 3.5527x; 1.0785x over previous
#include <cuda_runtime.h>
#include <cuda_bf16.h>
#include <math.h>
#include <stdint.h>

#define HW 96
#define C0 720
#define M_TOT 18432
#define KC 6480                      // 9*720
#define NPROTO 20
#define BM 128
#define BN 144
#define BK 48
#define ROWB 112                     // 48 bf16 = 96B + 16B pad
#define A_PL (128*ROWB)              // 14336
#define B_PL (144*ROWB)              // 16128
#define STG (2*A_PL + 2*B_PL)        // 60928
#define NSTAGE 3
#define SMEM_DYN (NSTAGE*STG)        // 182784
#define NCHUNK 3264                  // 16B chunks per stage: A 2*128*6 + B 2*144*6

__device__ __nv_bfloat16 g_fh[M_TOT*C0], g_fl[M_TOT*C0];
__device__ __nv_bfloat16 g_wch[C0*KC], g_wcl[C0*KC];
__device__ __nv_bfloat16 g_w1h[C0*C0], g_w1l[C0*C0];
__device__ __nv_bfloat16 g_w2h[C0*C0], g_w2l[C0*C0];
__device__ __nv_bfloat16 g_ch[M_TOT*C0], g_cl[M_TOT*C0];
__device__ __nv_bfloat16 g_p1h[M_TOT*C0], g_p1l[M_TOT*C0];
__device__ float g_p2[M_TOT*C0];
__device__ float g_s1[C0], g_t1[C0], g_s2[C0], g_t2[C0];
__device__ float g_proton[NPROTO*C0];

__device__ __forceinline__ uint32_t smem_u32(const void* p){
    uint32_t a;
    asm("{ .reg .u64 t; cvta.to.shared.u64 t, %1; cvt.u32.u64 %0, t; }" : "=r"(a) : "l"(p));
    return a;
}
__device__ __forceinline__ void ldsm4(uint32_t* r, uint32_t a){
    asm volatile("ldmatrix.sync.aligned.m8n8.x4.shared.b16 {%0,%1,%2,%3}, [%4];"
        : "=r"(r[0]), "=r"(r[1]), "=r"(r[2]), "=r"(r[3]) : "r"(a));
}
__device__ __forceinline__ void ldsm2(uint32_t* r, uint32_t a){
    asm volatile("ldmatrix.sync.aligned.m8n8.x2.shared.b16 {%0,%1}, [%2];"
        : "=r"(r[0]), "=r"(r[1]) : "r"(a));
}
__device__ __forceinline__ void mma16816(float* c, const uint32_t* a, const uint32_t* b){
    asm volatile("mma.sync.aligned.m16n8k16.row.col.f32.bf16.bf16.f32 "
        "{%0,%1,%2,%3}, {%4,%5,%6,%7}, {%8,%9}, {%0,%1,%2,%3};"
        : "+f"(c[0]), "+f"(c[1]), "+f"(c[2]), "+f"(c[3])
        : "r"(a[0]), "r"(a[1]), "r"(a[2]), "r"(a[3]), "r"(b[0]), "r"(b[1]));
}
__device__ __forceinline__ void cpa16(uint32_t dst, const void* src, int sz){
    asm volatile("cp.async.cg.shared.global [%0], [%1], 16, %2;" :: "r"(dst), "l"(src), "r"(sz));
}
__device__ __forceinline__ void split_bf(float v, __nv_bfloat16& h, __nv_bfloat16& l){
    h = __float2bfloat16(v); l = __float2bfloat16(v - __bfloat162float(h));
}

// ---------------- concat + bilinear (align_corners=True) ----------------
__device__ __forceinline__ float bilerp(const float* __restrict__ s, int b, int Ci, int c, int S, int y, int x){
    float sc = (float)(S-1)/(float)(HW-1);
    float fy = y*sc, fx = x*sc;
    int y0 = (int)floorf(fy), x0 = (int)floorf(fx);
    int y1 = min(y0+1, S-1), x1 = min(x0+1, S-1);
    float wy = fy-y0, wx = fx-x0;
    const float* p = s + ((b*Ci+c)*S)*S;
    float v00=p[y0*S+x0], v01=p[y0*S+x1], v10=p[y1*S+x0], v11=p[y1*S+x1];
    return (v00*(1.f-wx)+v01*wx)*(1.f-wy) + (v10*(1.f-wx)+v11*wx)*wy;
}
__global__ void concat_kernel(const float* __restrict__ f1, const float* __restrict__ f2,
                              const float* __restrict__ f3, const float* __restrict__ f4){
    int idx = blockIdx.x*blockDim.x + threadIdx.x;
    if (idx >= M_TOT*C0) return;
    int c = idx % C0, m = idx / C0;
    int x = m%HW, y = (m/HW)%HW, b = m/(HW*HW);
    float v;
    if (c < 48)       v = f1[((b*48+c)*HW+y)*HW+x];
    else if (c < 144) v = bilerp(f2,b, 96,c-48, 48,y,x);
    else if (c < 336) v = bilerp(f3,b,192,c-144,24,y,x);
    else              v = bilerp(f4,b,384,c-336,12,y,x);
    __nv_bfloat16 h,l; split_bf(v,h,l);
    g_fh[idx]=h; g_fl[idx]=l;
}

// ---------------- prep ----------------
__global__ void prep_w3(const float* __restrict__ w){
    int idx = blockIdx.x*blockDim.x + threadIdx.x;
    if (idx >= C0*KC) return;
    int cout = idx / KC, k = idx % KC;
    int q = k / C0, cin = k % C0;
    float v = w[(cout*C0+cin)*9+q];
    __nv_bfloat16 h,l; split_bf(v,h,l);
    g_wch[idx]=h; g_wcl[idx]=l;
}
__global__ void prep_w1x1(const float* __restrict__ w1, const float* __restrict__ w2){
    int idx = blockIdx.x*blockDim.x + threadIdx.x;
    if (idx >= C0*C0) return;
    int cout = idx / C0, cin = idx % C0;
    __nv_bfloat16 h,l;
    split_bf(w1[cout*C0+cin],h,l); g_w1h[idx]=h; g_w1l[idx]=l;
    split_bf(w2[cout*C0+cin],h,l); g_w2h[idx]=h; g_w2l[idx]=l;
}
__global__ void prep_bn(const float* __restrict__ cb, const float* __restrict__ g1, const float* __restrict__ b1,
                        const float* __restrict__ rm1, const float* __restrict__ rv1, const float* __restrict__ pb1,
                        const float* __restrict__ g2, const float* __restrict__ b2,
                        const float* __restrict__ rm2, const float* __restrict__ rv2){
    int n = blockIdx.x*blockDim.x + threadIdx.x;
    if (n >= C0) return;
    float s1 = g1[n]*rsqrtf(rv1[n]+1e-5f);
    g_s1[n]=s1; g_t1[n]=(cb[n]-rm1[n])*s1+b1[n];
    float s2 = g2[n]*rsqrtf(rv2[n]+1e-5f);
    g_s2[n]=s2; g_t2[n]=(pb1[n]-rm2[n])*s2+b2[n];
}
__global__ void prep_proto(const float* __restrict__ pr){
    int w = blockIdx.x, lane = threadIdx.x & 31;
    float ss = 0.f;
    for (int i=lane;i<C0;i+=32){ float v=pr[w*C0+i]; ss+=v*v; }
    #pragma unroll
    for (int o=16;o;o>>=1) ss += __shfl_xor_sync(0xffffffffu, ss, o);
    float inv = 1.f/fmaxf(sqrtf(ss),1e-12f);
    for (int i=lane;i<C0;i+=32) g_proton[w*C0+i] = pr[w*C0+i]*inv;
}

// ---------------- bf16 mma.sync GEMM, 3xBF16 split, 3-stage cp.async ----------------
template<int MODE>
__global__ __launch_bounds__(256,1) void gemm_mma(const float* __restrict__ pb2){
    extern __shared__ __align__(128) char smem[];
    const uint32_t su = smem_u32(smem);
    const int tid = threadIdx.x, lane = tid&31, wid = tid>>5;
    const int wm = wid&3, wn = wid>>2;          // 4 x 2 warp grid
    const int m0 = blockIdx.y*BM, n0 = blockIdx.x*BN;
    const int Kdim = (MODE==0)? KC : C0;
    const int nIter = Kdim/BK;                  // 135 or 15

    const char* pAh = (const char*)((MODE==0)? g_fh : (MODE==1)? g_ch : g_p1h);
    const char* pAl = (const char*)((MODE==0)? g_fl : (MODE==1)? g_cl : g_p1l);
    const char* pBh = (const char*)((MODE==0)? g_wch : (MODE==1)? g_w1h : g_w2h);
    const char* pBl = (const char*)((MODE==0)? g_wcl : (MODE==1)? g_w1l : g_w2l);

    // per-slot precompute: 13 chunk slots per thread (3264 chunks)
    bool valid[13], isA[13], plane[13];
    int dstv[13], srcb[13], pyv[13], pxv[13], cch[13];
    #pragma unroll
    for (int p=0;p<13;p++){
        int i = tid + p*256;
        valid[p] = (i < NCHUNK);
        isA[p]=false; plane[p]=false; dstv[p]=0; srcb[p]=0; pyv[p]=0; pxv[p]=0; cch[p]=0;
        if (!valid[p]) continue;
        if (i < 1536){
            isA[p] = true;
            int pl = (i>=768), j = i - pl*768;
            int r = j/6, c = j - 6*r;
            plane[p] = pl;
            dstv[p] = pl*A_PL + r*ROWB + c*16;
            cch[p] = c;
            int m = m0 + r;
            if (MODE==0){
                int b = m/(HW*HW), rm = m%(HW*HW);
                int y = rm/HW, x = rm%HW;
                pyv[p]=y; pxv[p]=x;
                srcb[p] = ((b*HW+y)*HW+x)*C0*2;   // pixel base bytes
            } else {
                srcb[p] = m*C0*2 + c*16;
            }
        } else {
            int ib = i-1536;
            int pl = (ib>=864), jb = ib - pl*864;
            int r = jb/6, c = jb - 6*r;
            plane[p] = pl;
            dstv[p] = 2*A_PL + pl*B_PL + r*ROWB + c*16;
            srcb[p] = (n0+r)*Kdim*2 + c*16;
        }
    }

    auto load_stage = [&](int it){
        uint32_t sb = su + (it % NSTAGE)*STG;
        int addK = it*BK*2;    // bytes
        #pragma unroll
        for (int p=0;p<13;p++){
            if (!valid[p]) continue;
            uint32_t dst = sb + dstv[p];
            if (isA[p]){
                if (MODE==0){
                    int k = it*BK + cch[p]*8;
                    int tap = k / C0;            // const-div
                    int cin = k - tap*C0;
                    int dy = tap/3 - 1, dx = tap - (tap/3)*3 - 1;
                    int yy = pyv[p]+dy, xx = pxv[p]+dx;
                    int sz = (((unsigned)yy < HW) && ((unsigned)xx < HW)) ? 16 : 0;
                    const char* src = (plane[p]? pAl : pAh) + srcb[p] + ((dy*HW+dx)*C0 + cin)*2;
                    if (!sz) src = (const char*)pAh;
                    cpa16(dst, src, sz);
                } else {
                    cpa16(dst, (plane[p]? pAl : pAh) + srcb[p] + addK, 16);
                }
            } else {
                cpa16(dst, (plane[p]? pBl : pBh) + srcb[p] + addK, 16);
            }
        }
        asm volatile("cp.async.commit_group;" ::: "memory");
    };

    float acc[2][9][4];
    #pragma unroll
    for (int a=0;a<2;a++)
        #pragma unroll
        for (int b=0;b<9;b++)
            #pragma unroll
            for (int c=0;c<4;c++) acc[a][b][c]=0.f;

    load_stage(0);
    load_stage(1);

    for (int it=0; it<nIter; ++it){
        if (it == nIter-1) asm volatile("cp.async.wait_group 0;" ::: "memory");
        else               asm volatile("cp.async.wait_group 1;" ::: "memory");
        __syncthreads();
        if (it+2 < nIter) load_stage(it+2);

        uint32_t sb = su + (it % NSTAGE)*STG;
        #pragma unroll
        for (int k16=0;k16<3;k16++){
            uint32_t ah[2][4], al[2][4];
            #pragma unroll
            for (int mt=0;mt<2;mt++){
                uint32_t row = wm*32 + mt*16 + (lane&15);
                uint32_t ad = sb + row*ROWB + k16*32 + (lane>>4)*16;
                ldsm4(ah[mt], ad);
                ldsm4(al[mt], ad + A_PL);
            }
            #pragma unroll
            for (int np=0;np<5;np++){
                if (np<4){
                    uint32_t n = wn*72 + np*16 + (lane>>4)*8 + (lane&7);
                    uint32_t ad = sb + 2*A_PL + n*ROWB + k16*32 + ((lane>>3)&1)*16;
                    uint32_t bh[4], bl[4];
                    ldsm4(bh, ad);
                    ldsm4(bl, ad + B_PL);
                    #pragma unroll
                    for (int h=0;h<2;h++){
                        int nt = np*2+h;
                        #pragma unroll
                        for (int mt=0;mt<2;mt++){
                            mma16816(acc[mt][nt], ah[mt], bh+2*h);
                            mma16816(acc[mt][nt], ah[mt], bl+2*h);
                            mma16816(acc[mt][nt], al[mt], bh+2*h);
                        }
                    }
                } else {
                    uint32_t n = wn*72 + 64 + (lane&7);
                    uint32_t ad = sb + 2*A_PL + n*ROWB + k16*32 + ((lane>>3)&1)*16;
                    uint32_t bh[2], bl[2];
                    ldsm2(bh, ad);
                    ldsm2(bl, ad + B_PL);
                    #pragma unroll
                    for (int mt=0;mt<2;mt++){
                        mma16816(acc[mt][8], ah[mt], bh);
                        mma16816(acc[mt][8], ah[mt], bl);
                        mma16816(acc[mt][8], al[mt], bh);
                    }
                }
            }
        }
    }

    // ---- epilogue ----
    #pragma unroll
    for (int mt=0;mt<2;mt++){
        #pragma unroll
        for (int nt=0;nt<9;nt++){
            #pragma unroll
            for (int h=0;h<2;h++){
                int m = m0 + wm*32 + mt*16 + (lane>>2) + h*8;
                int n = n0 + wn*72 + nt*8 + (lane&3)*2;
                float v0 = acc[mt][nt][2*h], v1 = acc[mt][nt][2*h+1];
                if (MODE==2){
                    float2 o; o.x = v0 + pb2[n]; o.y = v1 + pb2[n+1];
                    *(float2*)(g_p2 + (long)m*C0 + n) = o;
                } else {
                    const float* S = (MODE==0)? g_s1 : g_s2;
                    const float* T = (MODE==0)? g_t1 : g_t2;
                    __nv_bfloat16* Oh = (MODE==0)? g_ch : g_p1h;
                    __nv_bfloat16* Ol = (MODE==0)? g_cl : g_p1l;
                    float r0 = fmaxf(fmaf(v0, S[n],   T[n]),   0.f);
                    float r1 = fmaxf(fmaf(v1, S[n+1], T[n+1]), 0.f);
                    __nv_bfloat16 h0,l0,h1,l1;
                    split_bf(r0,h0,l0); split_bf(r1,h1,l1);
                    uint32_t ph = (uint32_t)__bfloat16_as_ushort(h0) | ((uint32_t)__bfloat16_as_ushort(h1)<<16);
                    uint32_t plv = (uint32_t)__bfloat16_as_ushort(l0) | ((uint32_t)__bfloat16_as_ushort(l1)<<16);
                    *(uint32_t*)(Oh + (long)m*C0 + n) = ph;
                    *(uint32_t*)(Ol + (long)m*C0 + n) = plv;
                }
            }
        }
    }
}

// ---------------- head ----------------
__global__ void head_kernel(const float* __restrict__ lng, const float* __restrict__ lnb,
                            const float* __restrict__ lmg, const float* __restrict__ lmb,
                            float* __restrict__ out){
    int warp = (blockIdx.x*blockDim.x + threadIdx.x)>>5;
    int lane = threadIdx.x & 31;
    if (warp >= M_TOT) return;
    const float* row = g_p2 + (long)warp*C0;
    float v[23]; float s=0.f, ss=0.f;
    #pragma unroll
    for (int i=0;i<23;i++){
        int idx = lane + i*32;
        float x = (idx<C0)? row[idx] : 0.f;
        v[i]=x; s+=x; ss+=x*x;
    }
    #pragma unroll
    for (int o=16;o;o>>=1){ s+=__shfl_xor_sync(0xffffffffu,s,o); ss+=__shfl_xor_sync(0xffffffffu,ss,o); }
    float mu = s/(float)C0;
    float rstd = rsqrtf(ss/(float)C0 - mu*mu + 1e-5f);
    float q = 0.f;
    #pragma unroll
    for (int i=0;i<23;i++){
        int idx = lane + i*32;
        float x = (idx<C0)? (v[i]-mu)*rstd*lng[idx]+lnb[idx] : 0.f;
        v[i]=x; q+=x*x;
    }
    #pragma unroll
    for (int o=16;o;o>>=1) q+=__shfl_xor_sync(0xffffffffu,q,o);
    float inv = 1.f/fmaxf(sqrtf(q),1e-12f);
    float mx0=-1e30f, mx1=-1e30f;
    for (int p=0;p<NPROTO;p++){
        float d=0.f;
        const float* pp = g_proton + p*C0;
        #pragma unroll
        for (int i=0;i<23;i++){
            int idx = lane + i*32;
            if (idx<C0) d += v[i]*pp[idx];
        }
        #pragma unroll
        for (int o=16;o;o>>=1) d+=__shfl_xor_sync(0xffffffffu,d,o);
        d *= inv;
        if (p<10) mx0=fmaxf(mx0,d); else mx1=fmaxf(mx1,d);
    }
    if (lane==0){
        float mu2 = 0.5f*(mx0+mx1);
        float d0 = mx0-mu2, d1 = mx1-mu2;
        float r2 = rsqrtf(0.5f*(d0*d0+d1*d1)+1e-5f);
        int m = warp;
        int x = m%HW, y = (m/HW)%HW, b = m/(HW*HW);
        out[((b*2+0)*HW+y)*HW+x] = d0*r2*lmg[0]+lmb[0];
        out[((b*2+1)*HW+y)*HW+x] = d1*r2*lmg[1]+lmb[1];
    }
}

extern "C" void kernel_launch(void* const* d_in, const int* in_sizes, int n_in,
                              void* d_out, int out_size){
    const float* feat1=(const float*)d_in[0];  const float* feat2=(const float*)d_in[1];
    const float* feat3=(const float*)d_in[2];  const float* feat4=(const float*)d_in[3];
    const float* cls_w=(const float*)d_in[4];  const float* cls_b=(const float*)d_in[5];
    const float* cbn_g=(const float*)d_in[6];  const float* cbn_b=(const float*)d_in[7];
    const float* cbn_rm=(const float*)d_in[8]; const float* cbn_rv=(const float*)d_in[9];
    const float* pw1=(const float*)d_in[10];   const float* pb1=(const float*)d_in[11];
    const float* pbn_g=(const float*)d_in[12]; const float* pbn_b=(const float*)d_in[13];
    const float* pbn_rm=(const float*)d_in[14];const float* pbn_rv=(const float*)d_in[15];
    const float* pw2=(const float*)d_in[16];   const float* pb2=(const float*)d_in[17];
    const float* lnf_g=(const float*)d_in[18]; const float* lnf_b=(const float*)d_in[19];
    const float* lnm_g=(const float*)d_in[20]; const float* lnm_b=(const float*)d_in[21];
    const float* protos=(const float*)d_in[22];
    float* out = (float*)d_out;

    static int smem_set = 0;
    if (!smem_set){
        cudaFuncSetAttribute(gemm_mma<0>, cudaFuncAttributeMaxDynamicSharedMemorySize, SMEM_DYN);
        cudaFuncSetAttribute(gemm_mma<1>, cudaFuncAttributeMaxDynamicSharedMemorySize, SMEM_DYN);
        cudaFuncSetAttribute(gemm_mma<2>, cudaFuncAttributeMaxDynamicSharedMemorySize, SMEM_DYN);
        smem_set = 1;
    }

    // launch order: gemm<0> is the 6th launch -> profiled by ncu (-s 5 -c 1)
    concat_kernel<<<(M_TOT*C0+255)/256, 256>>>(feat1, feat2, feat3, feat4);
    prep_w3<<<(C0*KC+255)/256, 256>>>(cls_w);
    prep_w1x1<<<(C0*C0+255)/256, 256>>>(pw1, pw2);
    prep_bn<<<3, 256>>>(cls_b, cbn_g, cbn_b, cbn_rm, cbn_rv, pb1, pbn_g, pbn_b, pbn_rm, pbn_rv);
    prep_proto<<<NPROTO, 32>>>(protos);

    dim3 grid(5, M_TOT/BM);  // (5,144)
    gemm_mma<0><<<grid, 256, SMEM_DYN>>>(nullptr);
    gemm_mma<1><<<grid, 256, SMEM_DYN>>>(nullptr);
    gemm_mma<2><<<grid, 256, SMEM_DYN>>>(pb2);

    head_kernel<<<(M_TOT*32+255)/256, 256>>>(lnf_g, lnf_b, lnm_g, lnm_b, out);
    (void)in_sizes; (void)n_in; (void)out_size;
}